// round 11
// baseline (speedup 1.0000x reference)
#include <cuda_runtime.h>

#define MAXABS_BLOCKS 2048
// Front-of-x region (in float4 units) we want resident in L2 for the quant
// pass: 6291456 * 16B = 96 MiB < 126 MB L2.
#define FRONT4 6291456

// Scratch (written unconditionally each run -> no init kernel needed).
__device__ unsigned int g_partial[MAXABS_BLOCKS];
__device__ unsigned int g_max_bits;
__device__ unsigned int g_ticket;   // zero-init; reset each run by last block

__device__ __forceinline__ float hx_max4(float4 v) {
    return fmaxf(fmaxf(fabsf(v.x), fabsf(v.y)), fmaxf(fabsf(v.z), fabsf(v.w)));
}

// ---------------------------------------------------------------------------
// Pass 1: per-block max|x|, REVERSE traversal. The back 48 MiB (read first,
// never needed again) is read with __ldcs (evict-first) so it does not
// displace the front 96 MiB (read last, re-read immediately by the quant
// kernel) from L2. Last block folds the final reduction.
// ---------------------------------------------------------------------------
__global__ __launch_bounds__(256) void hx_maxabs_kernel(
    const float4* __restrict__ x, int n4) {
    float m = 0.0f;
    const int stride = gridDim.x * blockDim.x;
    const int split = n4 - FRONT4;   // i < split  <=>  address >= FRONT4
    int i = blockIdx.x * blockDim.x + threadIdx.x;

    // Back region: streaming (evict-first) loads.
    for (; i + 3 * stride < split; i += 4 * stride) {
        float4 a = __ldcs(&x[n4 - 1 - i]);
        float4 b = __ldcs(&x[n4 - 1 - (i + stride)]);
        float4 c = __ldcs(&x[n4 - 1 - (i + 2 * stride)]);
        float4 d = __ldcs(&x[n4 - 1 - (i + 3 * stride)]);
        m = fmaxf(m, fmaxf(fmaxf(hx_max4(a), hx_max4(b)),
                           fmaxf(hx_max4(c), hx_max4(d))));
    }
    for (; i < split; i += stride)
        m = fmaxf(m, hx_max4(__ldcs(&x[n4 - 1 - i])));

    // Front region: default policy (retain in L2 for the quant pass).
    for (; i + 3 * stride < n4; i += 4 * stride) {
        float4 a = x[n4 - 1 - i];
        float4 b = x[n4 - 1 - (i + stride)];
        float4 c = x[n4 - 1 - (i + 2 * stride)];
        float4 d = x[n4 - 1 - (i + 3 * stride)];
        m = fmaxf(m, fmaxf(fmaxf(hx_max4(a), hx_max4(b)),
                           fmaxf(hx_max4(c), hx_max4(d))));
    }
    for (; i < n4; i += stride)
        m = fmaxf(m, hx_max4(x[n4 - 1 - i]));

#pragma unroll
    for (int o = 16; o > 0; o >>= 1)
        m = fmaxf(m, __shfl_xor_sync(0xffffffffu, m, o));
    __shared__ float warpmax[8];
    __shared__ bool is_last;
    const int lane = threadIdx.x & 31, wid = threadIdx.x >> 5;
    if (lane == 0) warpmax[wid] = m;
    __syncthreads();
    if (threadIdx.x == 0) {
        float bm = warpmax[0];
#pragma unroll
        for (int w = 1; w < 8; ++w) bm = fmaxf(bm, warpmax[w]);
        g_partial[blockIdx.x] = __float_as_uint(bm);
        __threadfence();
        unsigned int t = atomicAdd(&g_ticket, 1u);
        is_last = (t == (unsigned int)(gridDim.x - 1));
    }
    __syncthreads();

    if (is_last) {
        float r = 0.0f;
#pragma unroll
        for (int k = 0; k < MAXABS_BLOCKS / 256; ++k)
            r = fmaxf(r, __uint_as_float(g_partial[threadIdx.x + 256 * k]));
#pragma unroll
        for (int o = 16; o > 0; o >>= 1)
            r = fmaxf(r, __shfl_xor_sync(0xffffffffu, r, o));
        if (lane == 0) warpmax[wid] = r;
        __syncthreads();
        if (threadIdx.x == 0) {
            float bm = warpmax[0];
#pragma unroll
            for (int w = 1; w < 8; ++w) bm = fmaxf(bm, warpmax[w]);
            g_max_bits = __float_as_uint(bm);
            g_ticket = 0u;   // graph-replay determinism
        }
    }
}

// Single-MUFU approximate reciprocal (what __fdividef uses internally).
__device__ __forceinline__ float hx_rcp(float x) {
    float r;
    asm("rcp.approx.f32 %0, %1;" : "=f"(r) : "f"(x));
    return r;
}

// Lean tanh for the scalar M: exp2 (MUFU.EX2) + rcp divide, ~2 ulp.
__device__ __forceinline__ float hx_tanh(float x) {
    float cx = fminf(x, 30.0f);
    float e  = exp2f(cx * 2.8853900817779268f);     // exp(2*x)
    return __fdividef(e - 1.0f, e + 1.0f);
}

// Descending comparator on floats (2x FMNMX).
#define HX_CSWAP(a, b) { float _hi = fmaxf(a, b); b = fminf(a, b); a = _hi; }

// ---------------------------------------------------------------------------
// Pass 2: quantize + per-group (8 channels, stride 9) top-4 keep.
// Each block stages 4608 contiguous floats (64 segments of 72 = 8ch x 9hw)
// in SMEM via 4 front-batched float4 loads per thread (MLP_p1=4); each of
// 288 threads owns TWO groups of 8 stride-9 cells.
// Serial chain per element: EX2 -> FADD -> RCP(approx) -> FFMA -> FRND.
// ---------------------------------------------------------------------------
__global__ __launch_bounds__(288, 6) void hx_quant_kernel(
    const float* __restrict__ x, float* __restrict__ out,
    const int* __restrict__ bits_ptr) {
    __shared__ __align__(16) float tile[4608];
    const int tid = threadIdx.x;
    const long long blk = (long long)blockIdx.x * 4608;
    const float4* in4 = (const float4*)(x + blk);
    float4* out4 = (float4*)(out + blk);
    float4* t4 = (float4*)tile;

    // 4 front-batched 16B loads per thread (1152 float4 per block).
    t4[tid]       = in4[tid];
    t4[tid + 288] = in4[tid + 288];
    t4[tid + 576] = in4[tid + 576];
    t4[tid + 864] = in4[tid + 864];
    __syncthreads();

    const float delta     = (float)((1 << (bits_ptr[0] - 1)) - 1);  // 127
    const float M         = hx_tanh(fabsf(__uint_as_float(g_max_bits)));
    const float s         = __fdiv_rn(delta, M);
    const float n2s       = -2.0f * s;
    const float inv_delta = __fdiv_rn(1.0f, delta);
    const float K2        = 2.8853900817779268f;    // 2*log2(e)

    const int seg  = tid / 9;          // 0..31
    const int hw   = tid - seg * 9;    // 0..8

#pragma unroll
    for (int g = 0; g < 2; ++g) {
        const int base = (seg + 32 * g) * 72 + hw;

        float vf[8];     // rounded quantized value (integer-valued float)
        float key[8];    // |vf|*8 + (7-k): exact in fp32, all distinct
#pragma unroll
        for (int k = 0; k < 8; ++k) {
            float xx = tile[base + 9 * k];
            float e  = exp2f(fminf(xx, 30.0f) * K2);    // exp(2x)
            // s*tanh(x) = s - 2s/(e+1), approximate single-MUFU reciprocal
            float v  = rintf(fmaf(n2s, hx_rcp(e + 1.0f), s));
            vf[k]  = v;
            key[k] = fmaf(fabsf(v), 8.0f, (float)(7 - k));
        }

        // thr = 4th-largest key of 8: sort halves of 4 desc, merge-select.
        float a0 = key[0], a1 = key[1], a2 = key[2], a3 = key[3];
        float b0 = key[4], b1 = key[5], b2 = key[6], b3 = key[7];
        HX_CSWAP(a0, a1); HX_CSWAP(a2, a3); HX_CSWAP(a0, a2); HX_CSWAP(a1, a3); HX_CSWAP(a1, a2);
        HX_CSWAP(b0, b1); HX_CSWAP(b2, b3); HX_CSWAP(b0, b2); HX_CSWAP(b1, b3); HX_CSWAP(b1, b2);
        float thr = fmaxf(fmaxf(a3, b3),
                          fmaxf(fminf(a0, b2), fmaxf(fminf(a1, b1), fminf(a2, b0))));

#pragma unroll
        for (int i = 0; i < 8; ++i) {
            float sel = (key[i] >= thr) ? vf[i] : 0.0f;
            tile[base + 9 * i] = sel * inv_delta;
        }
    }
    __syncthreads();

    // Streaming stores: out is never re-read; keep x resident in L2.
    __stcs(&out4[tid],       t4[tid]);
    __stcs(&out4[tid + 288], t4[tid + 288]);
    __stcs(&out4[tid + 576], t4[tid + 576]);
    __stcs(&out4[tid + 864], t4[tid + 864]);
}

extern "C" void kernel_launch(void* const* d_in, const int* in_sizes, int n_in,
                              void* d_out, int out_size) {
    const float* x  = (const float*)d_in[0];
    const int* bits = (const int*)d_in[1];
    float* out      = (float*)d_out;

    const int n  = in_sizes[0];          // 37748736
    const int n4 = n >> 2;
    const int qblocks = n / 4608;        // 8192 (exact)

    hx_maxabs_kernel<<<MAXABS_BLOCKS, 256>>>((const float4*)x, n4);
    hx_quant_kernel<<<qblocks, 288>>>(x, out, bits);
}

// round 12
// speedup vs baseline: 1.3820x; 1.3820x over previous
#include <cuda_runtime.h>

// One full wave: 148 SMs x 8 resident blocks (256 thr, 25 regs) = 1184.
#define MAXABS_BLOCKS 1184

// Scratch (written unconditionally each run -> no init kernel needed).
__device__ unsigned int g_partial[MAXABS_BLOCKS];
__device__ unsigned int g_max_bits;
__device__ unsigned int g_ticket;   // zero-init; reset each run by last block

__device__ __forceinline__ float hx_max4(float4 v) {
    return fmaxf(fmaxf(fabsf(v.x), fabsf(v.y)), fmaxf(fabsf(v.z), fabsf(v.w)));
}

// ---------------------------------------------------------------------------
// Pass 1: per-block max|x|, REVERSE traversal (front of x stays in L2 for the
// quant kernel's forward read). Exactly one wave of blocks (no wave-2 tail).
// Last block folds the final reduction (no separate launch).
// ---------------------------------------------------------------------------
__global__ __launch_bounds__(256) void hx_maxabs_kernel(
    const float4* __restrict__ x, int n4) {
    float m = 0.0f;
    const int stride = gridDim.x * blockDim.x;
    int i = blockIdx.x * blockDim.x + threadIdx.x;
    for (; i + 3 * stride < n4; i += 4 * stride) {
        float4 a = x[n4 - 1 - i];
        float4 b = x[n4 - 1 - (i + stride)];
        float4 c = x[n4 - 1 - (i + 2 * stride)];
        float4 d = x[n4 - 1 - (i + 3 * stride)];
        m = fmaxf(m, fmaxf(fmaxf(hx_max4(a), hx_max4(b)),
                           fmaxf(hx_max4(c), hx_max4(d))));
    }
    for (; i < n4; i += stride)
        m = fmaxf(m, hx_max4(x[n4 - 1 - i]));

#pragma unroll
    for (int o = 16; o > 0; o >>= 1)
        m = fmaxf(m, __shfl_xor_sync(0xffffffffu, m, o));
    __shared__ float warpmax[8];
    __shared__ bool is_last;
    const int lane = threadIdx.x & 31, wid = threadIdx.x >> 5;
    if (lane == 0) warpmax[wid] = m;
    __syncthreads();
    if (threadIdx.x == 0) {
        float bm = warpmax[0];
#pragma unroll
        for (int w = 1; w < 8; ++w) bm = fmaxf(bm, warpmax[w]);
        g_partial[blockIdx.x] = __float_as_uint(bm);
        __threadfence();
        unsigned int t = atomicAdd(&g_ticket, 1u);
        is_last = (t == (unsigned int)(gridDim.x - 1));
    }
    __syncthreads();

    if (is_last) {
        float r = 0.0f;
        for (int k = threadIdx.x; k < MAXABS_BLOCKS; k += 256)
            r = fmaxf(r, __uint_as_float(g_partial[k]));
#pragma unroll
        for (int o = 16; o > 0; o >>= 1)
            r = fmaxf(r, __shfl_xor_sync(0xffffffffu, r, o));
        if (lane == 0) warpmax[wid] = r;
        __syncthreads();
        if (threadIdx.x == 0) {
            float bm = warpmax[0];
#pragma unroll
            for (int w = 1; w < 8; ++w) bm = fmaxf(bm, warpmax[w]);
            g_max_bits = __float_as_uint(bm);
            g_ticket = 0u;   // graph-replay determinism
        }
    }
}

// Single-MUFU approximate reciprocal (what __fdividef uses internally).
__device__ __forceinline__ float hx_rcp(float x) {
    float r;
    asm("rcp.approx.f32 %0, %1;" : "=f"(r) : "f"(x));
    return r;
}

// Lean tanh for the scalar M: exp2 (MUFU.EX2) + rcp divide, ~2 ulp.
__device__ __forceinline__ float hx_tanh(float x) {
    float cx = fminf(x, 30.0f);
    float e  = exp2f(cx * 2.8853900817779268f);     // exp(2*x)
    return __fdividef(e - 1.0f, e + 1.0f);
}

// Descending comparator on floats (2x FMNMX).
#define HX_CSWAP(a, b) { float _hi = fmaxf(a, b); b = fminf(a, b); a = _hi; }

// ---------------------------------------------------------------------------
// Pass 2: quantize + per-group (8 channels, stride 9) top-4 keep.
// Each block stages 4608 contiguous floats (64 segments of 72 = 8ch x 9hw)
// in SMEM via 4 front-batched float4 loads per thread (MLP_p1=4); each of
// 288 threads owns TWO groups of 8 stride-9 cells.
// Serial chain per element: EX2 -> FADD -> RCP(approx) -> FFMA -> FRND.
// ---------------------------------------------------------------------------
__global__ __launch_bounds__(288, 6) void hx_quant_kernel(
    const float* __restrict__ x, float* __restrict__ out,
    const int* __restrict__ bits_ptr) {
    __shared__ __align__(16) float tile[4608];
    const int tid = threadIdx.x;
    const long long blk = (long long)blockIdx.x * 4608;
    const float4* in4 = (const float4*)(x + blk);
    float4* out4 = (float4*)(out + blk);
    float4* t4 = (float4*)tile;

    // 4 front-batched 16B loads per thread (1152 float4 per block).
    t4[tid]       = in4[tid];
    t4[tid + 288] = in4[tid + 288];
    t4[tid + 576] = in4[tid + 576];
    t4[tid + 864] = in4[tid + 864];
    __syncthreads();

    const float delta     = (float)((1 << (bits_ptr[0] - 1)) - 1);  // 127
    const float M         = hx_tanh(fabsf(__uint_as_float(g_max_bits)));
    const float s         = __fdiv_rn(delta, M);
    const float n2s       = -2.0f * s;
    const float inv_delta = __fdiv_rn(1.0f, delta);
    const float K2        = 2.8853900817779268f;    // 2*log2(e)

    const int seg  = tid / 9;          // 0..31
    const int hw   = tid - seg * 9;    // 0..8

#pragma unroll
    for (int g = 0; g < 2; ++g) {
        const int base = (seg + 32 * g) * 72 + hw;

        float vf[8];     // rounded quantized value (integer-valued float)
        float key[8];    // |vf|*8 + (7-k): exact in fp32, all distinct
#pragma unroll
        for (int k = 0; k < 8; ++k) {
            float xx = tile[base + 9 * k];
            float e  = exp2f(fminf(xx, 30.0f) * K2);    // exp(2x)
            // s*tanh(x) = s - 2s/(e+1), approximate single-MUFU reciprocal
            float v  = rintf(fmaf(n2s, hx_rcp(e + 1.0f), s));
            vf[k]  = v;
            key[k] = fmaf(fabsf(v), 8.0f, (float)(7 - k));
        }

        // thr = 4th-largest key of 8: sort halves of 4 desc, merge-select.
        float a0 = key[0], a1 = key[1], a2 = key[2], a3 = key[3];
        float b0 = key[4], b1 = key[5], b2 = key[6], b3 = key[7];
        HX_CSWAP(a0, a1); HX_CSWAP(a2, a3); HX_CSWAP(a0, a2); HX_CSWAP(a1, a3); HX_CSWAP(a1, a2);
        HX_CSWAP(b0, b1); HX_CSWAP(b2, b3); HX_CSWAP(b0, b2); HX_CSWAP(b1, b3); HX_CSWAP(b1, b2);
        float thr = fmaxf(fmaxf(a3, b3),
                          fmaxf(fminf(a0, b2), fmaxf(fminf(a1, b1), fminf(a2, b0))));

#pragma unroll
        for (int i = 0; i < 8; ++i) {
            float sel = (key[i] >= thr) ? vf[i] : 0.0f;
            tile[base + 9 * i] = sel * inv_delta;
        }
    }
    __syncthreads();

    // Streaming stores: out is never re-read; keep x resident in L2.
    __stcs(&out4[tid],       t4[tid]);
    __stcs(&out4[tid + 288], t4[tid + 288]);
    __stcs(&out4[tid + 576], t4[tid + 576]);
    __stcs(&out4[tid + 864], t4[tid + 864]);
}

extern "C" void kernel_launch(void* const* d_in, const int* in_sizes, int n_in,
                              void* d_out, int out_size) {
    const float* x  = (const float*)d_in[0];
    const int* bits = (const int*)d_in[1];
    float* out      = (float*)d_out;

    const int n  = in_sizes[0];          // 37748736
    const int n4 = n >> 2;
    const int qblocks = n / 4608;        // 8192 (exact)

    hx_maxabs_kernel<<<MAXABS_BLOCKS, 256>>>((const float4*)x, n4);
    hx_quant_kernel<<<qblocks, 288>>>(x, out, bits);
}

// round 13
// speedup vs baseline: 1.3868x; 1.0034x over previous
#include <cuda_runtime.h>

// One full wave: 148 SMs x 8 resident blocks (256 thr, 25 regs) = 1184.
#define MAXABS_BLOCKS 1184

// Scratch (written unconditionally each run -> no init kernel needed).
__device__ unsigned int g_partial[MAXABS_BLOCKS];
__device__ unsigned int g_max_bits;
__device__ unsigned int g_ticket;   // zero-init; reset each run by last block

__device__ __forceinline__ float hx_max4(float4 v) {
    return fmaxf(fmaxf(fabsf(v.x), fabsf(v.y)), fmaxf(fabsf(v.z), fabsf(v.w)));
}

// ---------------------------------------------------------------------------
// Pass 1: per-block max|x|, REVERSE traversal (front of x stays in L2 for the
// quant kernel's forward read). Exactly one wave of blocks; last block folds
// the final reduction. (At the 151MB/6.3TB/s read floor — do not touch.)
// ---------------------------------------------------------------------------
__global__ __launch_bounds__(256) void hx_maxabs_kernel(
    const float4* __restrict__ x, int n4) {
    float m = 0.0f;
    const int stride = gridDim.x * blockDim.x;
    int i = blockIdx.x * blockDim.x + threadIdx.x;
    for (; i + 3 * stride < n4; i += 4 * stride) {
        float4 a = x[n4 - 1 - i];
        float4 b = x[n4 - 1 - (i + stride)];
        float4 c = x[n4 - 1 - (i + 2 * stride)];
        float4 d = x[n4 - 1 - (i + 3 * stride)];
        m = fmaxf(m, fmaxf(fmaxf(hx_max4(a), hx_max4(b)),
                           fmaxf(hx_max4(c), hx_max4(d))));
    }
    for (; i < n4; i += stride)
        m = fmaxf(m, hx_max4(x[n4 - 1 - i]));

#pragma unroll
    for (int o = 16; o > 0; o >>= 1)
        m = fmaxf(m, __shfl_xor_sync(0xffffffffu, m, o));
    __shared__ float warpmax[8];
    __shared__ bool is_last;
    const int lane = threadIdx.x & 31, wid = threadIdx.x >> 5;
    if (lane == 0) warpmax[wid] = m;
    __syncthreads();
    if (threadIdx.x == 0) {
        float bm = warpmax[0];
#pragma unroll
        for (int w = 1; w < 8; ++w) bm = fmaxf(bm, warpmax[w]);
        g_partial[blockIdx.x] = __float_as_uint(bm);
        __threadfence();
        unsigned int t = atomicAdd(&g_ticket, 1u);
        is_last = (t == (unsigned int)(gridDim.x - 1));
    }
    __syncthreads();

    if (is_last) {
        float r = 0.0f;
        for (int k = threadIdx.x; k < MAXABS_BLOCKS; k += 256)
            r = fmaxf(r, __uint_as_float(g_partial[k]));
#pragma unroll
        for (int o = 16; o > 0; o >>= 1)
            r = fmaxf(r, __shfl_xor_sync(0xffffffffu, r, o));
        if (lane == 0) warpmax[wid] = r;
        __syncthreads();
        if (threadIdx.x == 0) {
            float bm = warpmax[0];
#pragma unroll
            for (int w = 1; w < 8; ++w) bm = fmaxf(bm, warpmax[w]);
            g_max_bits = __float_as_uint(bm);
            g_ticket = 0u;   // graph-replay determinism
        }
    }
}

// Single-MUFU approximate reciprocal (what __fdividef uses internally).
__device__ __forceinline__ float hx_rcp(float x) {
    float r;
    asm("rcp.approx.f32 %0, %1;" : "=f"(r) : "f"(x));
    return r;
}

// Lean tanh for the scalar M: exp2 (MUFU.EX2) + rcp divide, ~2 ulp.
__device__ __forceinline__ float hx_tanh(float x) {
    float cx = fminf(x, 30.0f);
    float e  = exp2f(cx * 2.8853900817779268f);     // exp(2*x)
    return __fdividef(e - 1.0f, e + 1.0f);
}

// Descending comparator on floats (2x FMNMX).
#define HX_CSWAP(a, b) { float _hi = fmaxf(a, b); b = fminf(a, b); a = _hi; }

#define K2 2.8853900817779268f   // 2*log2(e)

// vf = rint(s*tanh(x)), serial chain EX2 -> FADD -> RCP -> FFMA -> FRND.
__device__ __forceinline__ float hx_quantize(float xx, float s, float n2s) {
    float e = exp2f(fminf(xx, 30.0f) * K2);
    return rintf(fmaf(n2s, hx_rcp(e + 1.0f), s));
}

// ---------------------------------------------------------------------------
// Pass 2, 3-phase structure:
//   A: each thread computes vf for its 16 contiguous elements IN REGISTERS
//      (MUFU chain overlaps global-load latency; no barrier upstream),
//      stores vf to SMEM with 4x STS.128.
//   B: each thread owns 2 groups (8 channels at stride 9): 8x LDS.32 of vf,
//      build keys, selection network -> per-group threshold (576/block).
//   C: each thread re-reads its 4 vf quads + 4 thresholds per quad, selects
//      in registers, STG.128 directly (no output SMEM round-trip).
// Key = |vf|*8 + (7-k), recomputed identically in B and C.
// ---------------------------------------------------------------------------
__global__ __launch_bounds__(288, 6) void hx_quant_kernel(
    const float* __restrict__ x, float* __restrict__ out,
    const int* __restrict__ bits_ptr) {
    __shared__ __align__(16) float vf_tile[4608];   // quantized values
    __shared__ float thr_tile[576];                 // per-group thresholds
    const int tid = threadIdx.x;
    const long long blk = (long long)blockIdx.x * 4608;
    const float4* in4 = (const float4*)(x + blk);
    float4* out4 = (float4*)(out + blk);
    float4* v4 = (float4*)vf_tile;

    const float delta     = (float)((1 << (bits_ptr[0] - 1)) - 1);  // 127
    const float M         = hx_tanh(fabsf(__uint_as_float(g_max_bits)));
    const float s         = __fdiv_rn(delta, M);
    const float n2s       = -2.0f * s;
    const float inv_delta = __fdiv_rn(1.0f, delta);

    // ---- Phase A: front-batched loads, elementwise quantize, stage vf ----
    {
        float4 a = in4[tid];
        float4 b = in4[tid + 288];
        float4 c = in4[tid + 576];
        float4 d = in4[tid + 864];
        a.x = hx_quantize(a.x, s, n2s); a.y = hx_quantize(a.y, s, n2s);
        a.z = hx_quantize(a.z, s, n2s); a.w = hx_quantize(a.w, s, n2s);
        b.x = hx_quantize(b.x, s, n2s); b.y = hx_quantize(b.y, s, n2s);
        b.z = hx_quantize(b.z, s, n2s); b.w = hx_quantize(b.w, s, n2s);
        c.x = hx_quantize(c.x, s, n2s); c.y = hx_quantize(c.y, s, n2s);
        c.z = hx_quantize(c.z, s, n2s); c.w = hx_quantize(c.w, s, n2s);
        d.x = hx_quantize(d.x, s, n2s); d.y = hx_quantize(d.y, s, n2s);
        d.z = hx_quantize(d.z, s, n2s); d.w = hx_quantize(d.w, s, n2s);
        v4[tid]       = a;
        v4[tid + 288] = b;
        v4[tid + 576] = c;
        v4[tid + 864] = d;
    }
    __syncthreads();

    // ---- Phase B: per-group threshold (4th-largest key of 8) ----
#pragma unroll
    for (int g = 0; g < 2; ++g) {
        const int gid  = 2 * tid + g;          // 0..575
        const int seg  = gid / 9;
        const int hw   = gid - 9 * seg;
        const int base = seg * 72 + hw;

        float key[8];
#pragma unroll
        for (int k = 0; k < 8; ++k) {
            float v = vf_tile[base + 9 * k];
            key[k] = fmaf(fabsf(v), 8.0f, (float)(7 - k));
        }
        float a0 = key[0], a1 = key[1], a2 = key[2], a3 = key[3];
        float b0 = key[4], b1 = key[5], b2 = key[6], b3 = key[7];
        HX_CSWAP(a0, a1); HX_CSWAP(a2, a3); HX_CSWAP(a0, a2); HX_CSWAP(a1, a3); HX_CSWAP(a1, a2);
        HX_CSWAP(b0, b1); HX_CSWAP(b2, b3); HX_CSWAP(b0, b2); HX_CSWAP(b1, b3); HX_CSWAP(b1, b2);
        thr_tile[gid] = fmaxf(fmaxf(a3, b3),
                              fmaxf(fminf(a0, b2), fmaxf(fminf(a1, b1), fminf(a2, b0))));
    }
    __syncthreads();

    // ---- Phase C: select + coalesced store straight from registers ----
    // Element e = 4*tid + c + 1152*j. 1152 % 72 == 0, 72 % 4 == 0, so within
    // a quad the segment is constant and (hw, k) per component are j-invariant.
    {
        const int e0   = 4 * tid;
        const int seg0 = e0 / 72;
        const int r0   = e0 - 72 * seg0;        // quad never crosses a segment
        int kc[4], hwc[4];
#pragma unroll
        for (int c = 0; c < 4; ++c) {
            int rc = r0 + c;
            kc[c]  = rc / 9;
            hwc[c] = rc - 9 * kc[c];
        }
#pragma unroll
        for (int j = 0; j < 4; ++j) {
            const float4 v = v4[tid + 288 * j];
            const int gbase = (seg0 + 16 * j) * 9;
            float4 o;
            {
                float key = fmaf(fabsf(v.x), 8.0f, (float)(7 - kc[0]));
                o.x = (key >= thr_tile[gbase + hwc[0]]) ? v.x * inv_delta : 0.0f;
            }
            {
                float key = fmaf(fabsf(v.y), 8.0f, (float)(7 - kc[1]));
                o.y = (key >= thr_tile[gbase + hwc[1]]) ? v.y * inv_delta : 0.0f;
            }
            {
                float key = fmaf(fabsf(v.z), 8.0f, (float)(7 - kc[2]));
                o.z = (key >= thr_tile[gbase + hwc[2]]) ? v.z * inv_delta : 0.0f;
            }
            {
                float key = fmaf(fabsf(v.w), 8.0f, (float)(7 - kc[3]));
                o.w = (key >= thr_tile[gbase + hwc[3]]) ? v.w * inv_delta : 0.0f;
            }
            __stcs(&out4[tid + 288 * j], o);   // evict-first: never re-read
        }
    }
}

extern "C" void kernel_launch(void* const* d_in, const int* in_sizes, int n_in,
                              void* d_out, int out_size) {
    const float* x  = (const float*)d_in[0];
    const int* bits = (const int*)d_in[1];
    float* out      = (float*)d_out;

    const int n  = in_sizes[0];          // 37748736
    const int n4 = n >> 2;
    const int qblocks = n / 4608;        // 8192 (exact)

    hx_maxabs_kernel<<<MAXABS_BLOCKS, 256>>>((const float4*)x, n4);
    hx_quant_kernel<<<qblocks, 288>>>(x, out, bits);
}

// round 14
// speedup vs baseline: 1.4062x; 1.0140x over previous
#include <cuda_runtime.h>

// One full wave: 148 SMs x 8 resident blocks (256 thr, 25 regs) = 1184.
#define MAXABS_BLOCKS 1184

// Scratch (written unconditionally each run -> no init kernel needed).
__device__ unsigned int g_partial[MAXABS_BLOCKS];
__device__ unsigned int g_max_bits;
__device__ unsigned int g_ticket;   // zero-init; reset each run by last block

__device__ __forceinline__ float hx_max4(float4 v) {
    return fmaxf(fmaxf(fabsf(v.x), fabsf(v.y)), fmaxf(fabsf(v.z), fabsf(v.w)));
}

// ---------------------------------------------------------------------------
// Pass 1: per-block max|x|, REVERSE traversal (front of x stays in L2 for the
// quant kernel's forward read). One wave of blocks; last block folds the
// final reduction. PDL trigger fires after the read loop so the quant grid
// can ramp up while the reduction tail drains.
// ---------------------------------------------------------------------------
__global__ __launch_bounds__(256) void hx_maxabs_kernel(
    const float4* __restrict__ x, int n4) {
    float m = 0.0f;
    const int stride = gridDim.x * blockDim.x;
    int i = blockIdx.x * blockDim.x + threadIdx.x;
    for (; i + 3 * stride < n4; i += 4 * stride) {
        float4 a = x[n4 - 1 - i];
        float4 b = x[n4 - 1 - (i + stride)];
        float4 c = x[n4 - 1 - (i + 2 * stride)];
        float4 d = x[n4 - 1 - (i + 3 * stride)];
        m = fmaxf(m, fmaxf(fmaxf(hx_max4(a), hx_max4(b)),
                           fmaxf(hx_max4(c), hx_max4(d))));
    }
    for (; i < n4; i += stride)
        m = fmaxf(m, hx_max4(x[n4 - 1 - i]));

    // PDL: allow the dependent quant kernel to begin launching now; its
    // grid-dependency sync still waits for this kernel's full completion
    // before reading g_max_bits.
    cudaTriggerProgrammaticLaunchCompletion();

#pragma unroll
    for (int o = 16; o > 0; o >>= 1)
        m = fmaxf(m, __shfl_xor_sync(0xffffffffu, m, o));
    __shared__ float warpmax[8];
    __shared__ bool is_last;
    const int lane = threadIdx.x & 31, wid = threadIdx.x >> 5;
    if (lane == 0) warpmax[wid] = m;
    __syncthreads();
    if (threadIdx.x == 0) {
        float bm = warpmax[0];
#pragma unroll
        for (int w = 1; w < 8; ++w) bm = fmaxf(bm, warpmax[w]);
        g_partial[blockIdx.x] = __float_as_uint(bm);
        __threadfence();
        unsigned int t = atomicAdd(&g_ticket, 1u);
        is_last = (t == (unsigned int)(gridDim.x - 1));
    }
    __syncthreads();

    if (is_last) {
        float r = 0.0f;
        for (int k = threadIdx.x; k < MAXABS_BLOCKS; k += 256)
            r = fmaxf(r, __uint_as_float(g_partial[k]));
#pragma unroll
        for (int o = 16; o > 0; o >>= 1)
            r = fmaxf(r, __shfl_xor_sync(0xffffffffu, r, o));
        if (lane == 0) warpmax[wid] = r;
        __syncthreads();
        if (threadIdx.x == 0) {
            float bm = warpmax[0];
#pragma unroll
            for (int w = 1; w < 8; ++w) bm = fmaxf(bm, warpmax[w]);
            g_max_bits = __float_as_uint(bm);
            g_ticket = 0u;   // graph-replay determinism
        }
    }
}

// Single-MUFU approximate reciprocal (what __fdividef uses internally).
__device__ __forceinline__ float hx_rcp(float x) {
    float r;
    asm("rcp.approx.f32 %0, %1;" : "=f"(r) : "f"(x));
    return r;
}

// Lean tanh for the scalar M: exp2 (MUFU.EX2) + rcp divide, ~2 ulp.
__device__ __forceinline__ float hx_tanh(float x) {
    float cx = fminf(x, 30.0f);
    float e  = exp2f(cx * 2.8853900817779268f);     // exp(2*x)
    return __fdividef(e - 1.0f, e + 1.0f);
}

// Descending comparator on floats (2x FMNMX).
#define HX_CSWAP(a, b) { float _hi = fmaxf(a, b); b = fminf(a, b); a = _hi; }

#define K2 2.8853900817779268f   // 2*log2(e)

// vf = rint(s*tanh(x)), serial chain EX2 -> FADD -> RCP -> FFMA -> FRND.
__device__ __forceinline__ float hx_quantize(float xx, float s, float n2s) {
    float e = exp2f(fminf(xx, 30.0f) * K2);
    return rintf(fmaf(n2s, hx_rcp(e + 1.0f), s));
}

// ---------------------------------------------------------------------------
// Pass 2 (PDL secondary), 3-phase structure:
//   A: 4 front-batched LDG.128 issued BEFORE the grid-dependency sync (loads
//      of read-only x overlap the maxabs tail), then sync, then elementwise
//      quantize in registers and stage vf via 4x STS.128.
//   B: each thread owns 2 groups (8 ch at stride 9): selection network ->
//      per-group threshold (576/block).
//   C: re-read own vf quads + thresholds, select in registers, STG.128.
// Key = |vf|*8 + (7-k), recomputed identically in B and C.
// ---------------------------------------------------------------------------
__global__ __launch_bounds__(288, 6) void hx_quant_kernel(
    const float* __restrict__ x, float* __restrict__ out,
    const int* __restrict__ bits_ptr) {
    __shared__ __align__(16) float vf_tile[4608];   // quantized values
    __shared__ float thr_tile[576];                 // per-group thresholds
    const int tid = threadIdx.x;
    const long long blk = (long long)blockIdx.x * 4608;
    const float4* in4 = (const float4*)(x + blk);
    float4* out4 = (float4*)(out + blk);
    float4* v4 = (float4*)vf_tile;

    // Issue the global loads first: x is read-only, safe before the sync.
    float4 a = in4[tid];
    float4 b = in4[tid + 288];
    float4 c = in4[tid + 576];
    float4 d = in4[tid + 864];
    const int bits = bits_ptr[0];

    // Wait for the maxabs kernel's writes (g_max_bits) to be visible.
    cudaGridDependencySynchronize();

    const float delta     = (float)((1 << (bits - 1)) - 1);         // 127
    const float M         = hx_tanh(fabsf(__uint_as_float(g_max_bits)));
    const float s         = __fdiv_rn(delta, M);
    const float n2s       = -2.0f * s;
    const float inv_delta = __fdiv_rn(1.0f, delta);

    // ---- Phase A: elementwise quantize, stage vf ----
    a.x = hx_quantize(a.x, s, n2s); a.y = hx_quantize(a.y, s, n2s);
    a.z = hx_quantize(a.z, s, n2s); a.w = hx_quantize(a.w, s, n2s);
    b.x = hx_quantize(b.x, s, n2s); b.y = hx_quantize(b.y, s, n2s);
    b.z = hx_quantize(b.z, s, n2s); b.w = hx_quantize(b.w, s, n2s);
    c.x = hx_quantize(c.x, s, n2s); c.y = hx_quantize(c.y, s, n2s);
    c.z = hx_quantize(c.z, s, n2s); c.w = hx_quantize(c.w, s, n2s);
    d.x = hx_quantize(d.x, s, n2s); d.y = hx_quantize(d.y, s, n2s);
    d.z = hx_quantize(d.z, s, n2s); d.w = hx_quantize(d.w, s, n2s);
    v4[tid]       = a;
    v4[tid + 288] = b;
    v4[tid + 576] = c;
    v4[tid + 864] = d;
    __syncthreads();

    // ---- Phase B: per-group threshold (4th-largest key of 8) ----
#pragma unroll
    for (int g = 0; g < 2; ++g) {
        const int gid  = 2 * tid + g;          // 0..575
        const int seg  = gid / 9;
        const int hw   = gid - 9 * seg;
        const int base = seg * 72 + hw;

        float key[8];
#pragma unroll
        for (int k = 0; k < 8; ++k) {
            float v = vf_tile[base + 9 * k];
            key[k] = fmaf(fabsf(v), 8.0f, (float)(7 - k));
        }
        float a0 = key[0], a1 = key[1], a2 = key[2], a3 = key[3];
        float b0 = key[4], b1 = key[5], b2 = key[6], b3 = key[7];
        HX_CSWAP(a0, a1); HX_CSWAP(a2, a3); HX_CSWAP(a0, a2); HX_CSWAP(a1, a3); HX_CSWAP(a1, a2);
        HX_CSWAP(b0, b1); HX_CSWAP(b2, b3); HX_CSWAP(b0, b2); HX_CSWAP(b1, b3); HX_CSWAP(b1, b2);
        thr_tile[gid] = fmaxf(fmaxf(a3, b3),
                              fmaxf(fminf(a0, b2), fmaxf(fminf(a1, b1), fminf(a2, b0))));
    }
    __syncthreads();

    // ---- Phase C: select + coalesced store straight from registers ----
    // Element e = 4*tid + comp + 1152*j. 1152 % 72 == 0, 72 % 4 == 0: a quad
    // never crosses a segment and (hw, k) per component are j-invariant.
    {
        const int e0   = 4 * tid;
        const int seg0 = e0 / 72;
        const int r0   = e0 - 72 * seg0;
        int kc[4], hwc[4];
#pragma unroll
        for (int comp = 0; comp < 4; ++comp) {
            int rc = r0 + comp;
            kc[comp]  = rc / 9;
            hwc[comp] = rc - 9 * kc[comp];
        }
#pragma unroll
        for (int j = 0; j < 4; ++j) {
            const float4 v = v4[tid + 288 * j];
            const int gbase = (seg0 + 16 * j) * 9;
            float4 o;
            {
                float key = fmaf(fabsf(v.x), 8.0f, (float)(7 - kc[0]));
                o.x = (key >= thr_tile[gbase + hwc[0]]) ? v.x * inv_delta : 0.0f;
            }
            {
                float key = fmaf(fabsf(v.y), 8.0f, (float)(7 - kc[1]));
                o.y = (key >= thr_tile[gbase + hwc[1]]) ? v.y * inv_delta : 0.0f;
            }
            {
                float key = fmaf(fabsf(v.z), 8.0f, (float)(7 - kc[2]));
                o.z = (key >= thr_tile[gbase + hwc[2]]) ? v.z * inv_delta : 0.0f;
            }
            {
                float key = fmaf(fabsf(v.w), 8.0f, (float)(7 - kc[3]));
                o.w = (key >= thr_tile[gbase + hwc[3]]) ? v.w * inv_delta : 0.0f;
            }
            __stcs(&out4[tid + 288 * j], o);   // evict-first: never re-read
        }
    }
}

extern "C" void kernel_launch(void* const* d_in, const int* in_sizes, int n_in,
                              void* d_out, int out_size) {
    const float* x  = (const float*)d_in[0];
    const int* bits = (const int*)d_in[1];
    float* out      = (float*)d_out;

    const int n  = in_sizes[0];          // 37748736
    const int n4 = n >> 2;
    const int qblocks = n / 4608;        // 8192 (exact)

    hx_maxabs_kernel<<<MAXABS_BLOCKS, 256>>>((const float4*)x, n4);

    // Quant kernel with Programmatic Dependent Launch: starts ramping while
    // the maxabs tail drains; cudaGridDependencySynchronize() inside guards
    // the g_max_bits read.
    cudaLaunchAttribute attrs[1];
    attrs[0].id = cudaLaunchAttributeProgrammaticStreamSerialization;
    attrs[0].val.programmaticStreamSerializationAllowed = 1;
    cudaLaunchConfig_t cfg = {};
    cfg.gridDim  = dim3((unsigned)qblocks, 1, 1);
    cfg.blockDim = dim3(288, 1, 1);
    cfg.dynamicSmemBytes = 0;
    cfg.stream = 0;
    cfg.attrs = attrs;
    cfg.numAttrs = 1;
    cudaLaunchKernelEx(&cfg, hx_quant_kernel, x, out, bits);
}